// round 8
// baseline (speedup 1.0000x reference)
#include <cuda_runtime.h>
#include <cuda_bf16.h>
#include <cstdint>

#define NN 50000
#define NE 500000
#define DD 128
#define BN_EPS_F 1e-5f
#define NBLK_SCAN 196
#define TILES 782              // ceil(50000/64)

// smem layout (bytes): 64-row A tiles, full 128-row B tiles, stride 272 B (136 halfs)
#define SM_AHI 0
#define SM_ALO 17408
#define SM_BHI 34816
#define SM_BLO 69632
#define SM_BIAS 104448         // 256 floats
#define SM_PS   105472         // 2 x 128 floats
#define SM_QS   106496         // 2 x 128 floats
#define TC_SMEM 107520

// ---------------- device scratch ----------------
__device__ __align__(16) float g_ha[NN * DD];
__device__ __align__(16) float g_hb[NN * DD];
__device__ __align__(16) float g_bn[2 * DD];
__device__ float g_out_norm[NN];
__device__ float g_in_norm[NN];
__device__ int   g_deg[2 * NN];
__device__ int   g_rowptr[NN + 1];
__device__ int   g_fill[NN];
__device__ int   g_col[NE];
__device__ int   g_blk[256];
__device__ float g_stats[2 * DD];
// padded bf16 weight images: [layer][z][ hi 34816B | lo 34816B ], Bt[n][k] 136-half rows
__device__ __align__(16) char g_wimg[6 * 69632];

// ---------------- helpers ----------------
__device__ __forceinline__ float relu(float x) { return fmaxf(x, 0.f); }
__device__ __forceinline__ uint32_t bfpair(float x, float y) {
    __nv_bfloat162 t = __floats2bfloat162_rn(x, y);
    return *reinterpret_cast<uint32_t*>(&t);
}
__device__ __forceinline__ uint32_t smem_u32(const void* p) {
    uint32_t a;
    asm("{ .reg .u64 t; cvta.to.shared.u64 t, %1; cvt.u32.u64 %0, t; }" : "=r"(a) : "l"(p));
    return a;
}
#define MMA(d, a0, a1, a2, a3, b0, b1) \
    asm volatile("mma.sync.aligned.m16n8k16.row.col.f32.bf16.bf16.f32 " \
        "{%0,%1,%2,%3}, {%4,%5,%6,%7}, {%8,%9}, {%0,%1,%2,%3};" \
        : "+f"((d)[0]), "+f"((d)[1]), "+f"((d)[2]), "+f"((d)[3]) \
        : "r"(a0), "r"(a1), "r"(a2), "r"(a3), "r"(b0), "r"(b1))
#define LDSM4(r, a) \
    asm volatile("ldmatrix.sync.aligned.m8n8.x4.shared.b16 {%0,%1,%2,%3}, [%4];" \
        : "=r"((r)[0]), "=r"((r)[1]), "=r"((r)[2]), "=r"((r)[3]) : "r"(a))

// ---------------- prep kernels ----------------
__global__ void init_deg_kernel() {
    int i = blockIdx.x * 256 + threadIdx.x;
    if (i < 2 * NN) g_deg[i] = 0;
    if (i < DD) { g_bn[i] = 1.f; g_bn[DD + i] = 0.f; g_stats[i] = 0.f; g_stats[DD + i] = 0.f; }
}
__global__ void count_deg_kernel(const int* __restrict__ src, const int* __restrict__ dst) {
    int e = blockIdx.x * 256 + threadIdx.x;
    if (e < NE) { atomicAdd(&g_deg[src[e]], 1); atomicAdd(&g_deg[NN + dst[e]], 1); }
}
__global__ void norms_kernel() {
    int i = blockIdx.x * 256 + threadIdx.x;
    if (i < NN) {
        int d0 = g_deg[i], d1 = g_deg[NN + i];
        g_out_norm[i] = d0 > 0 ? rsqrtf((float)d0) : 0.f;
        g_in_norm[i]  = d1 > 0 ? rsqrtf((float)d1) : 0.f;
    }
}
__global__ void scanA_kernel() {
    __shared__ int s[256];
    int t = threadIdx.x, b = blockIdx.x, i = b * 256 + t;
    int d = (i < NN) ? g_deg[NN + i] : 0;
    s[t] = d; __syncthreads();
    #pragma unroll
    for (int off = 1; off < 256; off <<= 1) {
        int v = (t >= off) ? s[t - off] : 0; __syncthreads();
        s[t] += v; __syncthreads();
    }
    if (i < NN) g_rowptr[i] = s[t] - d;
    if (t == 255) g_blk[b] = s[255];
}
__global__ void scanB_kernel() {
    __shared__ int s[256];
    int t = threadIdx.x;
    int d = (t < NBLK_SCAN) ? g_blk[t] : 0;
    s[t] = d; __syncthreads();
    #pragma unroll
    for (int off = 1; off < 256; off <<= 1) {
        int v = (t >= off) ? s[t - off] : 0; __syncthreads();
        s[t] += v; __syncthreads();
    }
    g_blk[t] = s[t] - d;
}
__global__ void scanC_kernel() {
    int i = blockIdx.x * 256 + threadIdx.x;
    if (i < NN) { int rp = g_rowptr[i] + g_blk[i >> 8]; g_rowptr[i] = rp; g_fill[i] = rp; }
    if (i == 0) g_rowptr[NN] = NE;
}
__global__ void fill_kernel(const int* __restrict__ src, const int* __restrict__ dst) {
    int e = blockIdx.x * 256 + threadIdx.x;
    if (e < NE) g_col[atomicAdd(&g_fill[dst[e]], 1)] = src[e];
}
__global__ void embed_kernel(const int* __restrict__ node_ids, const float* __restrict__ emb) {
    int idx = blockIdx.x * 256 + threadIdx.x;
    int row = idx >> 5, c = idx & 31;
    reinterpret_cast<float4*>(g_ha)[idx] = reinterpret_cast<const float4*>(emb)[node_ids[row] * 32 + c];
}
__global__ void prep_weights(const float* __restrict__ Ws, const float* __restrict__ Rws) {
    int t = blockIdx.x * 256 + threadIdx.x;
    if (t >= 6 * 128 * 136) return;
    int kk = t % 136, r = t / 136;
    int n = r & 127; r >>= 7;
    int z = r & 1, l = r >> 1;
    float hi = 0.f, lo = 0.f;
    if (kk < 128) {
        float v = (z ? Rws : Ws)[l * 16384 + kk * 128 + n];
        __nv_bfloat16 h = __float2bfloat16(v);
        hi = __bfloat162float(h);
        lo = v - hi;
    }
    __nv_bfloat16* img = reinterpret_cast<__nv_bfloat16*>(g_wimg + (size_t)(l * 2 + z) * 69632);
    img[n * 136 + kk] = __float2bfloat16(hi);
    img[17408 + n * 136 + kk] = __float2bfloat16(lo);
}

// ---------------- fused gather + HMMA dual GEMM + epilogue + stats ----------------
__global__ void __launch_bounds__(256, 2)
gemm_kernel(const float* __restrict__ IN, float* __restrict__ OUT, int layer,
            const float* __restrict__ bvec, const float* __restrict__ rbvec,
            int do_stats) {
    extern __shared__ char smc[];
    const uint32_t ub = smem_u32(smc);
    float* sbias = reinterpret_cast<float*>(smc + SM_BIAS);
    float* ps    = reinterpret_cast<float*>(smc + SM_PS);
    float* qs    = reinterpret_cast<float*>(smc + SM_QS);

    const int tid = threadIdx.x, lane = tid & 31, wid = tid >> 5;
    const int mw = wid & 1, nw = wid >> 1;       // 2 row-warps x 4 col-warps
    const int base = blockIdx.x * 64;

    if (tid < 128) { sbias[tid] = bvec[tid]; sbias[128 + tid] = rbvec[tid]; }

    // per-warp ldmatrix base addresses
    const uint32_t aBase = ub + SM_AHI
        + (uint32_t)(mw * 32 + (lane & 15)) * 272 + (uint32_t)(lane >> 4) * 16;
    const uint32_t bBase = ub + SM_BHI
        + (uint32_t)(nw * 32 + ((lane & 7) | ((lane >> 4) << 3))) * 272
        + (uint32_t)((lane >> 3) & 1) * 16;

    float s[8], sq[8];
    #pragma unroll
    for (int i = 0; i < 8; i++) { s[i] = 0.f; sq[i] = 0.f; }

    const float4* x4  = reinterpret_cast<const float4*>(IN);
    const float4* BN4 = reinterpret_cast<const float4*>(g_bn);

    for (int z = 0; z < 2; z++) {
        // ---- stage B: contiguous copy of pre-split padded image (hi|lo, 69632 B) ----
        {
            const float4* wsrc = reinterpret_cast<const float4*>(g_wimg + (size_t)(layer * 2 + z) * 69632);
            float4* bdst = reinterpret_cast<float4*>(smc + SM_BHI);
            #pragma unroll
            for (int i = 0; i < 17; i++) bdst[tid + i * 256] = wsrc[tid + i * 256];
        }
        if (z == 0) {
            // ---- stage A by CSR gather: warp w gathers rows w*8..w*8+7, lane = feature quad ----
            float4 sc = BN4[lane], sh = BN4[32 + lane];
            #pragma unroll 2
            for (int rr = 0; rr < 8; rr++) {
                int m = (wid << 3) + rr;
                int gr = base + m;
                float4 acc = make_float4(0.f, 0.f, 0.f, 0.f);
                float nsum = 0.f, inr = 0.f;
                if (gr < NN) {
                    inr = g_in_norm[gr];
                    int j = g_rowptr[gr], end = g_rowptr[gr + 1];
                    for (; j + 4 <= end; j += 4) {
                        int s0 = g_col[j], s1 = g_col[j + 1], s2 = g_col[j + 2], s3 = g_col[j + 3];
                        float n0 = g_out_norm[s0], n1 = g_out_norm[s1];
                        float n2 = g_out_norm[s2], n3 = g_out_norm[s3];
                        float4 v0 = x4[s0 * 32 + lane], v1 = x4[s1 * 32 + lane];
                        float4 v2 = x4[s2 * 32 + lane], v3 = x4[s3 * 32 + lane];
                        acc.x += n0 * v0.x + n1 * v1.x + n2 * v2.x + n3 * v3.x;
                        acc.y += n0 * v0.y + n1 * v1.y + n2 * v2.y + n3 * v3.y;
                        acc.z += n0 * v0.z + n1 * v1.z + n2 * v2.z + n3 * v3.z;
                        acc.w += n0 * v0.w + n1 * v1.w + n2 * v2.w + n3 * v3.w;
                        nsum += n0 + n1 + n2 + n3;
                    }
                    for (; j < end; j++) {
                        int sN = g_col[j]; float on = g_out_norm[sN];
                        float4 v = x4[sN * 32 + lane];
                        acc.x = fmaf(on, v.x, acc.x); acc.y = fmaf(on, v.y, acc.y);
                        acc.z = fmaf(on, v.z, acc.z); acc.w = fmaf(on, v.w, acc.w);
                        nsum += on;
                    }
                }
                float ox = inr * fmaf(sc.x, acc.x, sh.x * nsum);
                float oy = inr * fmaf(sc.y, acc.y, sh.y * nsum);
                float oz = inr * fmaf(sc.z, acc.z, sh.z * nsum);
                float ow = inr * fmaf(sc.w, acc.w, sh.w * nsum);
                float h0 = __bfloat162float(__float2bfloat16(ox));
                float h1 = __bfloat162float(__float2bfloat16(oy));
                float h2 = __bfloat162float(__float2bfloat16(oz));
                float h3 = __bfloat162float(__float2bfloat16(ow));
                char* pa = smc + SM_AHI + m * 272 + lane * 8;
                *reinterpret_cast<uint2*>(pa) = make_uint2(bfpair(h0, h1), bfpair(h2, h3));
                *reinterpret_cast<uint2*>(pa + 17408) =
                    make_uint2(bfpair(ox - h0, oy - h1), bfpair(oz - h2, ow - h3));
            }
        } else {
            // ---- stage A: 64 rows of affine(IN) -> bf16 hi/lo ----
            #pragma unroll
            for (int i = 0; i < 8; i++) {
                int qq = tid + i * 256;                // 0..2047
                int m = qq >> 5, c = qq & 31;
                int gr = base + m;
                float4 v = make_float4(0.f, 0.f, 0.f, 0.f);
                if (gr < NN) {
                    v = x4[gr * 32 + c];
                    float4 sc = BN4[c], sh = BN4[32 + c];
                    v.x = fmaf(v.x, sc.x, sh.x); v.y = fmaf(v.y, sc.y, sh.y);
                    v.z = fmaf(v.z, sc.z, sh.z); v.w = fmaf(v.w, sc.w, sh.w);
                }
                float h0 = __bfloat162float(__float2bfloat16(v.x));
                float h1 = __bfloat162float(__float2bfloat16(v.y));
                float h2 = __bfloat162float(__float2bfloat16(v.z));
                float h3 = __bfloat162float(__float2bfloat16(v.w));
                char* pa = smc + SM_AHI + m * 272 + c * 8;
                *reinterpret_cast<uint2*>(pa) = make_uint2(bfpair(h0, h1), bfpair(h2, h3));
                *reinterpret_cast<uint2*>(pa + 17408) =
                    make_uint2(bfpair(v.x - h0, v.y - h1), bfpair(v.z - h2, v.w - h3));
            }
        }
        __syncthreads();

        float acc[2][4][4];
        #pragma unroll
        for (int f = 0; f < 2; f++)
            #pragma unroll
            for (int g = 0; g < 4; g++)
                #pragma unroll
                for (int e = 0; e < 4; e++) acc[f][g][e] = 0.f;

        #pragma unroll
        for (int ks = 0; ks < 8; ks++) {
            uint32_t ah[2][4], al[2][4], bh[2][4], bl[2][4];
            #pragma unroll
            for (int f = 0; f < 2; f++) {
                uint32_t a = aBase + f * 4352 + ks * 32;
                LDSM4(ah[f], a);
                LDSM4(al[f], a + 17408);
            }
            #pragma unroll
            for (int gp = 0; gp < 2; gp++) {
                uint32_t b = bBase + gp * 4352 + ks * 32;
                LDSM4(bh[gp], b);
                LDSM4(bl[gp], b + 34816);
            }
            #pragma unroll
            for (int f = 0; f < 2; f++)
                #pragma unroll
                for (int gp = 0; gp < 2; gp++)
                    #pragma unroll
                    for (int gs = 0; gs < 2; gs++) {
                        float* d = acc[f][2 * gp + gs];
                        MMA(d, ah[f][0], ah[f][1], ah[f][2], ah[f][3],
                            bh[gp][2 * gs], bh[gp][2 * gs + 1]);
                        MMA(d, ah[f][0], ah[f][1], ah[f][2], ah[f][3],
                            bl[gp][2 * gs], bl[gp][2 * gs + 1]);
                        MMA(d, al[f][0], al[f][1], al[f][2], al[f][3],
                            bh[gp][2 * gs], bh[gp][2 * gs + 1]);
                    }
        }

        // ---- epilogue ----
        const int r = lane >> 2, q2 = (lane & 3) * 2;
        if (z == 0) {
            #pragma unroll
            for (int f = 0; f < 2; f++)
                #pragma unroll
                for (int g = 0; g < 4; g++) {
                    int row = mw * 32 + f * 16 + r;
                    int col = nw * 32 + g * 8 + q2;
                    float b0 = sbias[col], b1 = sbias[col + 1];
                    int gr = base + row;
                    if (gr < NN)
                        *reinterpret_cast<float2*>(&OUT[gr * DD + col]) =
                            make_float2(relu(acc[f][g][0] + b0), relu(acc[f][g][1] + b1));
                    if (gr + 8 < NN)
                        *reinterpret_cast<float2*>(&OUT[(gr + 8) * DD + col]) =
                            make_float2(relu(acc[f][g][2] + b0), relu(acc[f][g][3] + b1));
                }
        } else {
            #pragma unroll
            for (int f = 0; f < 2; f++)
                #pragma unroll
                for (int g = 0; g < 4; g++) {
                    int row = mw * 32 + f * 16 + r;
                    int col = nw * 32 + g * 8 + q2;
                    float rb0 = sbias[128 + col], rb1 = sbias[128 + col + 1];
                    int gr = base + row;
                    if (gr < NN) {
                        float2 c0 = *reinterpret_cast<const float2*>(&OUT[gr * DD + col]);
                        float h0 = c0.x + relu(acc[f][g][0] + rb0);
                        float h1 = c0.y + relu(acc[f][g][1] + rb1);
                        *reinterpret_cast<float2*>(&OUT[gr * DD + col]) = make_float2(h0, h1);
                        s[g * 2] += h0; s[g * 2 + 1] += h1;
                        sq[g * 2] += h0 * h0; sq[g * 2 + 1] += h1 * h1;
                    }
                    if (gr + 8 < NN) {
                        float2 c1 = *reinterpret_cast<const float2*>(&OUT[(gr + 8) * DD + col]);
                        float h2 = c1.x + relu(acc[f][g][2] + rb0);
                        float h3 = c1.y + relu(acc[f][g][3] + rb1);
                        *reinterpret_cast<float2*>(&OUT[(gr + 8) * DD + col]) = make_float2(h2, h3);
                        s[g * 2] += h2; s[g * 2 + 1] += h3;
                        sq[g * 2] += h2 * h2; sq[g * 2 + 1] += h3 * h3;
                    }
                }
        }
        __syncthreads();
    }

    if (do_stats) {
        #pragma unroll
        for (int i = 0; i < 8; i++) {
            #pragma unroll
            for (int off = 4; off < 32; off <<= 1) {
                s[i]  += __shfl_xor_sync(0xffffffffu, s[i], off);
                sq[i] += __shfl_xor_sync(0xffffffffu, sq[i], off);
            }
        }
        if (lane < 4) {
            #pragma unroll
            for (int g = 0; g < 4; g++) {
                int col = nw * 32 + g * 8 + lane * 2;
                ps[mw * 128 + col]     = s[g * 2];
                ps[mw * 128 + col + 1] = s[g * 2 + 1];
                qs[mw * 128 + col]     = sq[g * 2];
                qs[mw * 128 + col + 1] = sq[g * 2 + 1];
            }
        }
        __syncthreads();
        if (tid < 128) {
            atomicAdd(&g_stats[tid], ps[tid] + ps[128 + tid]);
            atomicAdd(&g_stats[DD + tid], qs[tid] + qs[128 + tid]);
        }
    }
}

// ---------------- batchnorm ----------------
__global__ void bn_stats_kernel(const float* __restrict__ gamma, const float* __restrict__ beta) {
    int c = threadIdx.x;
    float mu = g_stats[c] * (1.f / NN);
    float var = fmaxf(g_stats[DD + c] * (1.f / NN) - mu * mu, 0.f);
    float inv = gamma[c] * rsqrtf(var + BN_EPS_F);
    g_bn[c] = inv;
    g_bn[DD + c] = beta[c] - mu * inv;
    g_stats[c] = 0.f; g_stats[DD + c] = 0.f;
}

__global__ void bn_apply_kernel(const float* __restrict__ H, float* __restrict__ outp) {
    int idx = blockIdx.x * 256 + threadIdx.x;
    int c = (idx & 31) << 2;
    float4 h = reinterpret_cast<const float4*>(H)[idx];
    float4 o;
    o.x = h.x * g_bn[c + 0] + g_bn[DD + c + 0];
    o.y = h.y * g_bn[c + 1] + g_bn[DD + c + 1];
    o.z = h.z * g_bn[c + 2] + g_bn[DD + c + 2];
    o.w = h.w * g_bn[c + 3] + g_bn[DD + c + 3];
    reinterpret_cast<float4*>(outp)[idx] = o;
}

// ---------------- launch ----------------
extern "C" void kernel_launch(void* const* d_in, const int* in_sizes, int n_in,
                              void* d_out, int out_size) {
    const int*   node_ids = (const int*)d_in[0];
    const int*   src      = (const int*)d_in[1];
    const int*   dst      = (const int*)d_in[2];
    const float* emb      = (const float*)d_in[3];
    const float* Ws       = (const float*)d_in[4];
    const float* bs       = (const float*)d_in[5];
    const float* Rws      = (const float*)d_in[6];
    const float* Rbs      = (const float*)d_in[7];
    const float* gam      = (const float*)d_in[8];
    const float* bet      = (const float*)d_in[9];
    float* outp = (float*)d_out;

    float *p_ha, *p_hb;
    cudaGetSymbolAddress((void**)&p_ha, g_ha);
    cudaGetSymbolAddress((void**)&p_hb, g_hb);

    cudaFuncSetAttribute(gemm_kernel, cudaFuncAttributeMaxDynamicSharedMemorySize, TC_SMEM);

    const int NV4 = NN * DD / 4;
    init_deg_kernel<<<(2 * NN + 255) / 256, 256>>>();
    count_deg_kernel<<<(NE + 255) / 256, 256>>>(src, dst);
    norms_kernel<<<(NN + 255) / 256, 256>>>();
    scanA_kernel<<<NBLK_SCAN, 256>>>();
    scanB_kernel<<<1, 256>>>();
    scanC_kernel<<<(NN + 255) / 256, 256>>>();
    fill_kernel<<<(NE + 255) / 256, 256>>>(src, dst);
    embed_kernel<<<NV4 / 256, 256>>>(node_ids, emb);
    prep_weights<<<(6 * 128 * 136 + 255) / 256, 256>>>(Ws, Rws);

    for (int l = 0; l < 3; l++) {
        const float* IN = (l & 1) ? p_hb : p_ha;
        float* OUT = (l & 1) ? p_ha : p_hb;
        gemm_kernel<<<TILES, 256, TC_SMEM>>>(IN, OUT, l, bs + l * DD, Rbs + l * DD, 1);
        bn_stats_kernel<<<1, DD>>>(gam + l * DD, bet + l * DD);
    }
    bn_apply_kernel<<<NV4 / 256, 256>>>(p_hb, outp);
}

// round 10
// speedup vs baseline: 1.2207x; 1.2207x over previous
#include <cuda_runtime.h>
#include <cuda_bf16.h>
#include <cstdint>

#define NN 50000
#define NE 500000
#define DD 128
#define BN_EPS_F 1e-5f
#define NBLK_SCAN 196
#define NTILE 782              // ceil(50000/64)
#define GRID_G 296             // 148 SMs x 2 CTAs -> single wave

// smem layout (bytes): 64-row A tiles, full 128-row B tiles, stride 272 B (136 halfs)
#define SM_AHI 0
#define SM_ALO 17408
#define SM_BHI 34816
#define SM_BLO 69632
#define SM_BIAS 104448         // 256 floats
#define SM_PS   105472         // 2 x 128 floats
#define SM_QS   106496         // 2 x 128 floats
#define TC_SMEM 107520

// ---------------- device scratch ----------------
__device__ __align__(16) float g_ha[NN * DD];
__device__ __align__(16) float g_hb[NN * DD];
__device__ __align__(16) float g_agg[NN * DD];
__device__ __align__(16) float g_bn[2 * DD];
__device__ float g_out_norm[NN];
__device__ float g_in_norm[NN];
__device__ int   g_deg[2 * NN];
__device__ int   g_rowptr[NN + 1];
__device__ int   g_fill[NN];
__device__ int   g_col[NE];
__device__ int   g_blk[256];
__device__ float g_stats[2 * DD];
// padded bf16 weight images: [layer][z][ hi 34816B | lo 34816B ], Bt[n][k] 136-half rows
__device__ __align__(16) char g_wimg[6 * 69632];

// ---------------- helpers ----------------
__device__ __forceinline__ float relu(float x) { return fmaxf(x, 0.f); }
__device__ __forceinline__ uint32_t bfpair(float x, float y) {
    __nv_bfloat162 t = __floats2bfloat162_rn(x, y);
    return *reinterpret_cast<uint32_t*>(&t);
}
__device__ __forceinline__ uint32_t smem_u32(const void* p) {
    uint32_t a;
    asm("{ .reg .u64 t; cvta.to.shared.u64 t, %1; cvt.u32.u64 %0, t; }" : "=r"(a) : "l"(p));
    return a;
}
#define MMA(d, a0, a1, a2, a3, b0, b1) \
    asm volatile("mma.sync.aligned.m16n8k16.row.col.f32.bf16.bf16.f32 " \
        "{%0,%1,%2,%3}, {%4,%5,%6,%7}, {%8,%9}, {%0,%1,%2,%3};" \
        : "+f"((d)[0]), "+f"((d)[1]), "+f"((d)[2]), "+f"((d)[3]) \
        : "r"(a0), "r"(a1), "r"(a2), "r"(a3), "r"(b0), "r"(b1))
#define LDSM4(r, a) \
    asm volatile("ldmatrix.sync.aligned.m8n8.x4.shared.b16 {%0,%1,%2,%3}, [%4];" \
        : "=r"((r)[0]), "=r"((r)[1]), "=r"((r)[2]), "=r"((r)[3]) : "r"(a))

// ---------------- prep kernels ----------------
__global__ void init_deg_kernel() {
    int i = blockIdx.x * 256 + threadIdx.x;
    if (i < 2 * NN) g_deg[i] = 0;
    if (i < DD) { g_bn[i] = 1.f; g_bn[DD + i] = 0.f; g_stats[i] = 0.f; g_stats[DD + i] = 0.f; }
}
__global__ void count_deg_kernel(const int* __restrict__ src, const int* __restrict__ dst) {
    int e = blockIdx.x * 256 + threadIdx.x;
    if (e < NE) { atomicAdd(&g_deg[src[e]], 1); atomicAdd(&g_deg[NN + dst[e]], 1); }
}
__global__ void norms_kernel() {
    int i = blockIdx.x * 256 + threadIdx.x;
    if (i < NN) {
        int d0 = g_deg[i], d1 = g_deg[NN + i];
        g_out_norm[i] = d0 > 0 ? rsqrtf((float)d0) : 0.f;
        g_in_norm[i]  = d1 > 0 ? rsqrtf((float)d1) : 0.f;
    }
}
__global__ void scanA_kernel() {
    __shared__ int s[256];
    int t = threadIdx.x, b = blockIdx.x, i = b * 256 + t;
    int d = (i < NN) ? g_deg[NN + i] : 0;
    s[t] = d; __syncthreads();
    #pragma unroll
    for (int off = 1; off < 256; off <<= 1) {
        int v = (t >= off) ? s[t - off] : 0; __syncthreads();
        s[t] += v; __syncthreads();
    }
    if (i < NN) g_rowptr[i] = s[t] - d;
    if (t == 255) g_blk[b] = s[255];
}
__global__ void scanB_kernel() {
    __shared__ int s[256];
    int t = threadIdx.x;
    int d = (t < NBLK_SCAN) ? g_blk[t] : 0;
    s[t] = d; __syncthreads();
    #pragma unroll
    for (int off = 1; off < 256; off <<= 1) {
        int v = (t >= off) ? s[t - off] : 0; __syncthreads();
        s[t] += v; __syncthreads();
    }
    g_blk[t] = s[t] - d;
}
__global__ void scanC_kernel() {
    int i = blockIdx.x * 256 + threadIdx.x;
    if (i < NN) { int rp = g_rowptr[i] + g_blk[i >> 8]; g_rowptr[i] = rp; g_fill[i] = rp; }
    if (i == 0) g_rowptr[NN] = NE;
}
__global__ void fill_kernel(const int* __restrict__ src, const int* __restrict__ dst) {
    int e = blockIdx.x * 256 + threadIdx.x;
    if (e < NE) g_col[atomicAdd(&g_fill[dst[e]], 1)] = src[e];
}
__global__ void embed_kernel(const int* __restrict__ node_ids, const float* __restrict__ emb) {
    int idx = blockIdx.x * 256 + threadIdx.x;
    int row = idx >> 5, c = idx & 31;
    reinterpret_cast<float4*>(g_ha)[idx] = reinterpret_cast<const float4*>(emb)[node_ids[row] * 32 + c];
}
__global__ void prep_weights(const float* __restrict__ Ws, const float* __restrict__ Rws) {
    int t = blockIdx.x * 256 + threadIdx.x;
    if (t >= 6 * 128 * 136) return;
    int kk = t % 136, r = t / 136;
    int n = r & 127; r >>= 7;
    int z = r & 1, l = r >> 1;
    float hi = 0.f, lo = 0.f;
    if (kk < 128) {
        float v = (z ? Rws : Ws)[l * 16384 + kk * 128 + n];
        __nv_bfloat16 h = __float2bfloat16(v);
        hi = __bfloat162float(h);
        lo = v - hi;
    }
    __nv_bfloat16* img = reinterpret_cast<__nv_bfloat16*>(g_wimg + (size_t)(l * 2 + z) * 69632);
    img[n * 136 + kk] = __float2bfloat16(hi);
    img[17408 + n * 136 + kk] = __float2bfloat16(lo);
}

// ---------------- gather with fused BN affine ----------------
__global__ void gather_kernel(const float* __restrict__ IN) {
    int nid = blockIdx.x * 8 + (threadIdx.x >> 5);
    if (nid >= NN) return;
    int lane = threadIdx.x & 31;
    int j = g_rowptr[nid], end = g_rowptr[nid + 1];
    const float4* x4 = reinterpret_cast<const float4*>(IN);
    float4 sc = reinterpret_cast<const float4*>(g_bn)[lane];
    float4 sh = reinterpret_cast<const float4*>(g_bn)[32 + lane];
    float4 acc = make_float4(0.f, 0.f, 0.f, 0.f);
    float nsum = 0.f;
    for (; j + 4 <= end; j += 4) {
        int s0 = g_col[j], s1 = g_col[j + 1], s2 = g_col[j + 2], s3 = g_col[j + 3];
        float n0 = g_out_norm[s0], n1 = g_out_norm[s1], n2 = g_out_norm[s2], n3 = g_out_norm[s3];
        float4 v0 = x4[s0 * 32 + lane], v1 = x4[s1 * 32 + lane];
        float4 v2 = x4[s2 * 32 + lane], v3 = x4[s3 * 32 + lane];
        acc.x += n0 * v0.x + n1 * v1.x + n2 * v2.x + n3 * v3.x;
        acc.y += n0 * v0.y + n1 * v1.y + n2 * v2.y + n3 * v3.y;
        acc.z += n0 * v0.z + n1 * v1.z + n2 * v2.z + n3 * v3.z;
        acc.w += n0 * v0.w + n1 * v1.w + n2 * v2.w + n3 * v3.w;
        nsum += n0 + n1 + n2 + n3;
    }
    for (; j < end; j++) {
        int s = g_col[j]; float on = g_out_norm[s];
        float4 v = x4[s * 32 + lane];
        acc.x = fmaf(on, v.x, acc.x); acc.y = fmaf(on, v.y, acc.y);
        acc.z = fmaf(on, v.z, acc.z); acc.w = fmaf(on, v.w, acc.w);
        nsum += on;
    }
    float inr = g_in_norm[nid];
    float4 o;
    o.x = inr * fmaf(sc.x, acc.x, sh.x * nsum);
    o.y = inr * fmaf(sc.y, acc.y, sh.y * nsum);
    o.z = inr * fmaf(sc.z, acc.z, sh.z * nsum);
    o.w = inr * fmaf(sc.w, acc.w, sh.w * nsum);
    reinterpret_cast<float4*>(g_agg)[nid * 32 + lane] = o;
}

// ---------------- HMMA dual GEMM: 1-wave grid, multi-tile per B load ----------------
__global__ void __launch_bounds__(256, 2)
gemm_kernel(const float* __restrict__ A0, const float* __restrict__ IN,
            float* __restrict__ OUT, int layer,
            const float* __restrict__ bvec, const float* __restrict__ rbvec,
            int do_stats) {
    extern __shared__ char smc[];
    const uint32_t ub = smem_u32(smc);
    float* sbias = reinterpret_cast<float*>(smc + SM_BIAS);
    float* ps    = reinterpret_cast<float*>(smc + SM_PS);
    float* qs    = reinterpret_cast<float*>(smc + SM_QS);

    const int tid = threadIdx.x, lane = tid & 31, wid = tid >> 5;
    const int mw = wid & 1, nw = wid >> 1;       // 2 row-warps x 4 col-warps
    const int r = lane >> 2, q2 = (lane & 3) * 2;

    if (tid < 128) { sbias[tid] = bvec[tid]; sbias[128 + tid] = rbvec[tid]; }

    const uint32_t aBase = ub + SM_AHI
        + (uint32_t)(mw * 32 + (lane & 15)) * 272 + (uint32_t)(lane >> 4) * 16;
    const uint32_t bBase = ub + SM_BHI
        + (uint32_t)(nw * 32 + ((lane & 7) | ((lane >> 4) << 3))) * 272
        + (uint32_t)((lane >> 3) & 1) * 16;

    float s[8], sq[8];
    #pragma unroll
    for (int i = 0; i < 8; i++) { s[i] = 0.f; sq[i] = 0.f; }

    const float4* BN4 = reinterpret_cast<const float4*>(g_bn);

    for (int z = 0; z < 2; z++) {
        // ---- stage B once per z: contiguous copy of pre-split padded image ----
        {
            const float4* wsrc = reinterpret_cast<const float4*>(g_wimg + (size_t)(layer * 2 + z) * 69632);
            float4* bdst = reinterpret_cast<float4*>(smc + SM_BHI);
            #pragma unroll
            for (int i = 0; i < 17; i++) bdst[tid + i * 256] = wsrc[tid + i * 256];
        }
        const float4* A4 = reinterpret_cast<const float4*>(z ? IN : A0);

        for (int tile = blockIdx.x; tile < NTILE; tile += GRID_G) {
            const int base = tile * 64;
            // ---- stage A: 64 rows fp32 (+affine z=1) -> bf16 hi/lo ----
            #pragma unroll
            for (int i = 0; i < 8; i++) {
                int qq = tid + i * 256;                // 0..2047
                int m = qq >> 5, c = qq & 31;
                int gr = base + m;
                float4 v = make_float4(0.f, 0.f, 0.f, 0.f);
                if (gr < NN) {
                    v = A4[gr * 32 + c];
                    if (z) {
                        float4 sc = BN4[c], sh = BN4[32 + c];
                        v.x = fmaf(v.x, sc.x, sh.x); v.y = fmaf(v.y, sc.y, sh.y);
                        v.z = fmaf(v.z, sc.z, sh.z); v.w = fmaf(v.w, sc.w, sh.w);
                    }
                }
                float h0 = __bfloat162float(__float2bfloat16(v.x));
                float h1 = __bfloat162float(__float2bfloat16(v.y));
                float h2 = __bfloat162float(__float2bfloat16(v.z));
                float h3 = __bfloat162float(__float2bfloat16(v.w));
                char* pa = smc + SM_AHI + m * 272 + c * 8;
                *reinterpret_cast<uint2*>(pa) = make_uint2(bfpair(h0, h1), bfpair(h2, h3));
                *reinterpret_cast<uint2*>(pa + 17408) =
                    make_uint2(bfpair(v.x - h0, v.y - h1), bfpair(v.z - h2, v.w - h3));
            }
            __syncthreads();

            float acc[2][4][4];
            #pragma unroll
            for (int f = 0; f < 2; f++)
                #pragma unroll
                for (int g = 0; g < 4; g++)
                    #pragma unroll
                    for (int e = 0; e < 4; e++) acc[f][g][e] = 0.f;

            #pragma unroll
            for (int ks = 0; ks < 8; ks++) {
                uint32_t ah[2][4], al[2][4], bh[2][4], bl[2][4];
                #pragma unroll
                for (int f = 0; f < 2; f++) {
                    uint32_t a = aBase + f * 4352 + ks * 32;
                    LDSM4(ah[f], a);
                    LDSM4(al[f], a + 17408);
                }
                #pragma unroll
                for (int gp = 0; gp < 2; gp++) {
                    uint32_t b = bBase + gp * 4352 + ks * 32;
                    LDSM4(bh[gp], b);
                    LDSM4(bl[gp], b + 34816);
                }
                #pragma unroll
                for (int f = 0; f < 2; f++)
                    #pragma unroll
                    for (int gp = 0; gp < 2; gp++)
                        #pragma unroll
                        for (int gs = 0; gs < 2; gs++) {
                            float* d = acc[f][2 * gp + gs];
                            MMA(d, ah[f][0], ah[f][1], ah[f][2], ah[f][3],
                                bh[gp][2 * gs], bh[gp][2 * gs + 1]);
                            MMA(d, ah[f][0], ah[f][1], ah[f][2], ah[f][3],
                                bl[gp][2 * gs], bl[gp][2 * gs + 1]);
                            MMA(d, al[f][0], al[f][1], al[f][2], al[f][3],
                                bh[gp][2 * gs], bh[gp][2 * gs + 1]);
                        }
            }

            // ---- epilogue ----
            if (z == 0) {
                #pragma unroll
                for (int f = 0; f < 2; f++)
                    #pragma unroll
                    for (int g = 0; g < 4; g++) {
                        int row = mw * 32 + f * 16 + r;
                        int col = nw * 32 + g * 8 + q2;
                        float b0 = sbias[col], b1 = sbias[col + 1];
                        int gr = base + row;
                        if (gr < NN)
                            *reinterpret_cast<float2*>(&OUT[gr * DD + col]) =
                                make_float2(relu(acc[f][g][0] + b0), relu(acc[f][g][1] + b1));
                        if (gr + 8 < NN)
                            *reinterpret_cast<float2*>(&OUT[(gr + 8) * DD + col]) =
                                make_float2(relu(acc[f][g][2] + b0), relu(acc[f][g][3] + b1));
                    }
            } else {
                #pragma unroll
                for (int f = 0; f < 2; f++)
                    #pragma unroll
                    for (int g = 0; g < 4; g++) {
                        int row = mw * 32 + f * 16 + r;
                        int col = nw * 32 + g * 8 + q2;
                        float rb0 = sbias[128 + col], rb1 = sbias[128 + col + 1];
                        int gr = base + row;
                        if (gr < NN) {
                            float2 c0 = *reinterpret_cast<const float2*>(&OUT[gr * DD + col]);
                            float h0 = c0.x + relu(acc[f][g][0] + rb0);
                            float h1 = c0.y + relu(acc[f][g][1] + rb1);
                            *reinterpret_cast<float2*>(&OUT[gr * DD + col]) = make_float2(h0, h1);
                            s[g * 2] += h0; s[g * 2 + 1] += h1;
                            sq[g * 2] += h0 * h0; sq[g * 2 + 1] += h1 * h1;
                        }
                        if (gr + 8 < NN) {
                            float2 c1 = *reinterpret_cast<const float2*>(&OUT[(gr + 8) * DD + col]);
                            float h2 = c1.x + relu(acc[f][g][2] + rb0);
                            float h3 = c1.y + relu(acc[f][g][3] + rb1);
                            *reinterpret_cast<float2*>(&OUT[(gr + 8) * DD + col]) = make_float2(h2, h3);
                            s[g * 2] += h2; s[g * 2 + 1] += h3;
                            sq[g * 2] += h2 * h2; sq[g * 2 + 1] += h3 * h3;
                        }
                    }
            }
            __syncthreads();
        }
    }

    if (do_stats) {
        #pragma unroll
        for (int i = 0; i < 8; i++) {
            #pragma unroll
            for (int off = 4; off < 32; off <<= 1) {
                s[i]  += __shfl_xor_sync(0xffffffffu, s[i], off);
                sq[i] += __shfl_xor_sync(0xffffffffu, sq[i], off);
            }
        }
        if (lane < 4) {
            #pragma unroll
            for (int g = 0; g < 4; g++) {
                int col = nw * 32 + g * 8 + lane * 2;
                ps[mw * 128 + col]     = s[g * 2];
                ps[mw * 128 + col + 1] = s[g * 2 + 1];
                qs[mw * 128 + col]     = sq[g * 2];
                qs[mw * 128 + col + 1] = sq[g * 2 + 1];
            }
        }
        __syncthreads();
        if (tid < 128) {
            atomicAdd(&g_stats[tid], ps[tid] + ps[128 + tid]);
            atomicAdd(&g_stats[DD + tid], qs[tid] + qs[128 + tid]);
        }
    }
}

// ---------------- batchnorm ----------------
__global__ void bn_stats_kernel(const float* __restrict__ gamma, const float* __restrict__ beta) {
    int c = threadIdx.x;
    float mu = g_stats[c] * (1.f / NN);
    float var = fmaxf(g_stats[DD + c] * (1.f / NN) - mu * mu, 0.f);
    float inv = gamma[c] * rsqrtf(var + BN_EPS_F);
    g_bn[c] = inv;
    g_bn[DD + c] = beta[c] - mu * inv;
    g_stats[c] = 0.f; g_stats[DD + c] = 0.f;
}

__global__ void bn_apply_kernel(const float* __restrict__ H, float* __restrict__ outp) {
    int idx = blockIdx.x * 256 + threadIdx.x;
    int c = (idx & 31) << 2;
    float4 h = reinterpret_cast<const float4*>(H)[idx];
    float4 o;
    o.x = h.x * g_bn[c + 0] + g_bn[DD + c + 0];
    o.y = h.y * g_bn[c + 1] + g_bn[DD + c + 1];
    o.z = h.z * g_bn[c + 2] + g_bn[DD + c + 2];
    o.w = h.w * g_bn[c + 3] + g_bn[DD + c + 3];
    reinterpret_cast<float4*>(outp)[idx] = o;
}

// ---------------- launch ----------------
extern "C" void kernel_launch(void* const* d_in, const int* in_sizes, int n_in,
                              void* d_out, int out_size) {
    const int*   node_ids = (const int*)d_in[0];
    const int*   src      = (const int*)d_in[1];
    const int*   dst      = (const int*)d_in[2];
    const float* emb      = (const float*)d_in[3];
    const float* Ws       = (const float*)d_in[4];
    const float* bs       = (const float*)d_in[5];
    const float* Rws      = (const float*)d_in[6];
    const float* Rbs      = (const float*)d_in[7];
    const float* gam      = (const float*)d_in[8];
    const float* bet      = (const float*)d_in[9];
    float* outp = (float*)d_out;

    float *p_ha, *p_hb, *p_agg;
    cudaGetSymbolAddress((void**)&p_ha, g_ha);
    cudaGetSymbolAddress((void**)&p_hb, g_hb);
    cudaGetSymbolAddress((void**)&p_agg, g_agg);

    cudaFuncSetAttribute(gemm_kernel, cudaFuncAttributeMaxDynamicSharedMemorySize, TC_SMEM);

    const int NV4 = NN * DD / 4;
    init_deg_kernel<<<(2 * NN + 255) / 256, 256>>>();
    count_deg_kernel<<<(NE + 255) / 256, 256>>>(src, dst);
    norms_kernel<<<(NN + 255) / 256, 256>>>();
    scanA_kernel<<<NBLK_SCAN, 256>>>();
    scanB_kernel<<<1, 256>>>();
    scanC_kernel<<<(NN + 255) / 256, 256>>>();
    fill_kernel<<<(NE + 255) / 256, 256>>>(src, dst);
    embed_kernel<<<NV4 / 256, 256>>>(node_ids, emb);
    prep_weights<<<(6 * 128 * 136 + 255) / 256, 256>>>(Ws, Rws);

    for (int l = 0; l < 3; l++) {
        const float* IN = (l & 1) ? p_hb : p_ha;
        float* OUT = (l & 1) ? p_ha : p_hb;
        gather_kernel<<<(NN + 7) / 8, 256>>>(IN);
        gemm_kernel<<<GRID_G, 256, TC_SMEM>>>(p_agg, IN, OUT, l,
                                              bs + l * DD, Rbs + l * DD, 1);
        bn_stats_kernel<<<1, DD>>>(gam + l * DD, bet + l * DD);
    }
    bn_apply_kernel<<<NV4 / 256, 256>>>(p_hb, outp);
}